// round 4
// baseline (speedup 1.0000x reference)
#include <cuda_runtime.h>

// 3D neighborhood attention, B=2, H=W=T=64, C=96, NH=6, HD=16, KS=3 (27 window).
// Output: [B, NH*3, H, W, T] float32.
//
// Mapping: quad of 4 lanes = one (t, head). Lane c loads the c-th float4 of the
// 16-float head slice; dot4 partials butterfly-reduced in the quad.
// Quad ordering (head fastest) makes every warp LDG.128 a contiguous 512B load.
// Block = 32 t x 6 heads x 4 lanes = 768 threads; grid = B*H*W*(T/32) = 16384.

__global__ void __launch_bounds__(768)
natt3d_kernel(const float* __restrict__ q, const float* __restrict__ k,
              const float* __restrict__ rpb, float* __restrict__ out) {
    __shared__ float rpb_s[6 * 27];
    __shared__ float out_s[18 * 33];   // [channel-plane][t], padded stride 33

    const int tid = threadIdx.x;
    if (tid < 162) rpb_s[tid] = rpb[tid];

    const int c    = tid & 3;          // chunk within quad
    const int quad = tid >> 2;         // 0..191
    const int nh   = quad % 6;
    const int tl   = quad / 6;         // 0..31
    const int bx   = blockIdx.x;
    const int tb   = bx & 1;
    const int w    = (bx >> 1) & 63;
    const int h    = (bx >> 7) & 63;
    const int b    = bx >> 13;
    const int t    = tb * 32 + tl;

    const int pos  = ((b * 64 + h) * 64 + w) * 64 + t;
    const int base = pos * 96 + nh * 16 + c * 4;

    float4 qv = *reinterpret_cast<const float4*>(q + base);
    const float sc = 0.25f;            // HD^-0.5 = 16^-0.5
    qv.x *= sc; qv.y *= sc; qv.z *= sc; qv.w *= sc;

    const bool vh[3] = { h > 0, true, h < 63 };
    const bool vw[3] = { w > 0, true, w < 63 };
    const bool vt[3] = { t > 0, true, t < 63 };

    __syncthreads();

    float sum = 0.f, ax = 0.f, ay = 0.f, az = 0.f;

    #pragma unroll
    for (int n = 0; n < 27; ++n) {
        const int i = n / 9, j = (n / 3) % 3, l = n % 3;     // compile-time
        float p = 0.f;
        if (vh[i] && vw[j] && vt[l]) {
            const float4 kv = *reinterpret_cast<const float4*>(
                k + base + ((i - 1) * 4096 + (j - 1) * 64 + (l - 1)) * 96);
            p = qv.x * kv.x + qv.y * kv.y + qv.z * kv.z + qv.w * kv.w;
        }
        // quad butterfly: all 4 lanes get the full 16-wide dot
        p += __shfl_xor_sync(0xffffffffu, p, 1);
        p += __shfl_xor_sync(0xffffffffu, p, 2);
        // round-robin the exp/accumulate work across the quad
        if ((n & 3) == c) {
            const float e = __expf(p + rpb_s[nh * 27 + n]);
            sum += e;
            ax += e * (float)(i - 1);
            ay += e * (float)(j - 1);
            az += e * (float)(l - 1);
        }
    }

    sum += __shfl_xor_sync(0xffffffffu, sum, 1);
    sum += __shfl_xor_sync(0xffffffffu, sum, 2);
    ax  += __shfl_xor_sync(0xffffffffu, ax, 1);
    ax  += __shfl_xor_sync(0xffffffffu, ax, 2);
    ay  += __shfl_xor_sync(0xffffffffu, ay, 1);
    ay  += __shfl_xor_sync(0xffffffffu, ay, 2);
    az  += __shfl_xor_sync(0xffffffffu, az, 1);
    az  += __shfl_xor_sync(0xffffffffu, az, 2);

    const float inv = __fdividef(1.0f, sum);
    if (c < 3) {
        const float v = (c == 0) ? ax : (c == 1) ? ay : az;
        out_s[(nh * 3 + c) * 33 + tl] = v * inv;
    }
    __syncthreads();

    // coalesced store: 18 channel planes x 32 t; one warp = one plane's 128B run
    if (tid < 576) {
        const int pch = tid >> 5;      // 0..17  (nh*3 + component)
        const int t2  = tid & 31;
        out[(b * 18 + pch) * 262144 + h * 4096 + w * 64 + tb * 32 + t2]
            = out_s[pch * 33 + t2];
    }
}

extern "C" void kernel_launch(void* const* d_in, const int* in_sizes, int n_in,
                              void* d_out, int out_size) {
    const float* q   = (const float*)d_in[0];
    const float* k   = (const float*)d_in[1];
    const float* rpb = (const float*)d_in[2];
    float* out = (float*)d_out;
    natt3d_kernel<<<16384, 768>>>(q, k, rpb, out);
}